// round 15
// baseline (speedup 1.0000x reference)
#include <cuda_runtime.h>
#include <math.h>
#include <stdint.h>

constexpr int B  = 64;
constexpr int T  = 2048;
constexpr int D  = 128;
constexpr int H  = 256;
constexpr int H2 = 512;
constexpr float EPS = 1e-5f;

constexpr int NCTA = 128;   // 8 clusters x 16 CTAs
constexpr int NT   = 512;
constexpr int GR   = 8;
constexpr int BPG  = 8;
constexpr int CSZ  = 16;

// ---------------- device scratch ----------------
__device__ float g_h[GR * H * BPG];
__device__ float g_c[GR * H * BPG];
__device__ float g_part[(size_t)GR * 16 * H * BPG];

__global__ void k_init() { }
__global__ void k_dummy() { }

// ---------------- packed f32x2 helpers ----------------
__device__ __forceinline__ uint64_t pack2(float v) {
    uint64_t r;
    asm("mov.b64 %0, {%1, %1};" : "=l"(r) : "r"(__float_as_uint(v)));
    return r;
}
__device__ __forceinline__ void ffma2(uint64_t& a, uint64_t x, uint64_t y) {
    asm("fma.rn.f32x2 %0, %1, %2, %0;" : "+l"(a) : "l"(x), "l"(y));
}
__device__ __forceinline__ float2 unpk(uint64_t a) {
    float2 f;
    asm("mov.b64 {%0, %1}, %2;" : "=f"(f.x), "=f"(f.y) : "l"(a));
    return f;
}

// ---------------- fast transcendentals (safe saturation) ----------------
__device__ __forceinline__ float fsig(float v) {
    float e = __expf(-v);
    return __fdividef(1.f, 1.f + e);
}
__device__ __forceinline__ float ftanh(float v) {
    float e = __expf(-2.f * fabsf(v));
    float t = __fdividef(1.f - e, 1.f + e);
    return copysignf(t, v);
}

// ---------------- cluster mbarrier sync (data stays in L2) ----------------
__device__ __forceinline__ uint32_t smem_u32(const void* p) {
    uint32_t a;
    asm("{ .reg .u64 t; cvta.to.shared.u64 t, %1; cvt.u32.u64 %0, t; }"
        : "=r"(a) : "l"(p));
    return a;
}
// producers' named bar, then threads 0..15 arrive on peer tid's mbarrier
__device__ __forceinline__ void cl_arrive(uint32_t local_mbar, int nthr, int tid)
{
    asm volatile("bar.sync 1, %0;" :: "r"(nthr) : "memory");
    if (tid < CSZ) {
        uint32_t r;
        asm("mapa.shared::cluster.u32 %0, %1, %2;" : "=r"(r) : "r"(local_mbar), "r"(tid));
        asm volatile("mbarrier.arrive.release.cluster.shared::cluster.b64 _, [%0];"
                     :: "r"(r) : "memory");
    }
}
// all threads sleep-wait on the local mbarrier (per-thread acquire)
__device__ __forceinline__ void cl_wait(uint32_t mbar, uint32_t parity)
{
    asm volatile(
        "{\n\t.reg .pred P;\n\t"
        "W_%=:\n\t"
        "mbarrier.try_wait.parity.acquire.cluster.shared::cta.b64 P, [%0], %1, 0x989680;\n\t"
        "@P bra D_%=;\n\t"
        "bra W_%=;\n\t"
        "D_%=:\n\t}"
        :: "r"(mbar), "r"(parity) : "memory");
}

// ---------------- persistent scan, fused input projection ----------------
__global__ void __launch_bounds__(NT, 1) k_scan(
    const float* __restrict__ x,
    const float* __restrict__ Wi, const float* __restrict__ bi,
    const float* __restrict__ Wf, const float* __restrict__ bf,
    const float* __restrict__ Wc, const float* __restrict__ bc,
    const float* __restrict__ Wo, const float* __restrict__ bo,
    const float* __restrict__ Ui, const float* __restrict__ Uf,
    const float* __restrict__ Uc, const float* __restrict__ Uo,
    const float* __restrict__ K1, const float* __restrict__ kb1,
    const float* __restrict__ K2, const float* __restrict__ kb2,
    const float* __restrict__ gamma, const float* __restrict__ beta,
    float* __restrict__ out, int has_hc)
{
    extern __shared__ float sm[];
    uint64_t* mbars = (uint64_t*)sm;   // 3 mbarriers in first 16 floats
    float* sAct = sm + 16;        // 2048 activation staging [k*8+b]
    float* sRed = sAct + 2048;    // 4608 split-K partials
    float* sZp  = sRed + 4608;    //  256 z pair-interleaved [m'][8]
    float* sGU  = sZp + 256;      //   64
    float* sBU  = sGU + 64;       //   64
    float* sSt  = sBU + 64;       //  256 stats partials [16w][8b][2]
    float* sW   = sSt + 256;      // 8192 W slice [d][n'*4+g]
    float* sX   = sW  + 8192;     // 1024 x tile [d*8+b]
    float* sXP  = sX  + 1024;     // 4096 xproj partials [(dp*64+q)*8+b]

    const int tid = threadIdx.x;
    const int cta = blockIdx.x;
    const int cg  = cta & 15;     // == cluster ctarank
    const int bg  = cta >> 4;
    const int n0  = cg * 16;
    const int m0  = cg * 32;
    const int b0  = bg * 8;

    const uint32_t mbC = smem_u32(&mbars[0]);
    const uint32_t mbP = smem_u32(&mbars[1]);
    const uint32_t mbH = smem_u32(&mbars[2]);

    // producer roles
    const int p1q     = tid & 63;
    const int p1n     = p1q >> 2;
    const int p1g     = p1q & 3;
    const int p1chunk = tid >> 6;          // 8 x 32k
    const int p2m     = tid & 31;
    const int p2chunk = tid >> 5;          // 16 x 16k
    const int p3n     = tid & 255;
    const int p3mh    = tid >> 8;
    // owner role (idx<128)
    const int onn = tid >> 3;
    const int obb = tid & 7;
    // xproj producer role
    const int xc  = tid & 63;
    const int xdp = tid >> 6;

    // ---- weights into registers ----
    float wU[32], wK1[16], wK2[16];
    {
        const float* Up = (p1g == 0) ? Ui : (p1g == 1) ? Uf : (p1g == 2) ? Uc : Uo;
#pragma unroll
        for (int kk = 0; kk < 32; kk++) {
            int k = p1chunk * 32 + kk;
            wU[kk] = __ldg(&gamma[k]) * __ldg(&Up[(size_t)k * H + n0 + p1n]);
        }
#pragma unroll
        for (int kk = 0; kk < 16; kk++) {
            int k = p2chunk * 16 + kk;
            wK1[kk] = __ldg(&K1[(size_t)k * H2 + m0 + p2m]);
        }
#pragma unroll
        for (int mm = 0; mm < 16; mm++) {
            int m = m0 + p3mh * 16 + mm;
            wK2[mm] = __ldg(&K2[(size_t)m * H + p3n]);
        }
    }

    // ---- W slice into smem ----
    for (int idx = tid; idx < D * 64; idx += NT) {
        int d = idx >> 6, q = idx & 63, n = q >> 2, g = q & 3;
        const float* Wp = (g == 0) ? Wi : (g == 1) ? Wf : (g == 2) ? Wc : Wo;
        sW[idx] = __ldg(&Wp[(size_t)d * H + n0 + n]);
    }

    if (tid == 0) {
#pragma unroll
        for (int i = 0; i < 3; i++)
            asm volatile("mbarrier.init.shared.b64 [%0], %1;"
                         :: "r"(smem_u32(&mbars[i])), "r"(CSZ) : "memory");
    }

    if (tid < 64) {
        int n = tid >> 2, g = tid & 3;
        const float* Up = (g == 0) ? Ui : (g == 1) ? Uf : (g == 2) ? Uc : Uo;
        float s = 0.f, bs = 0.f;
        for (int k = 0; k < H; k++) {
            float u = __ldg(&Up[(size_t)k * H + n0 + n]);
            s  += __ldg(&gamma[k]) * u;
            bs += __ldg(&beta[k])  * u;
        }
        sGU[tid] = s; sBU[tid] = bs;
    }
    float rkb1 = 0.f;
    if (tid < 256) rkb1 = kb1[m0 + (tid >> 3)];

    // owner-thread constants + state
    float rkb2 = 0.f, rgam = 0.f, rbet = 0.f, rb4[4];
    float creg = 0.f, oreg = 0.f, xpv[4] = {0.f, 0.f, 0.f, 0.f};
    if (tid < 128) {
        rkb2 = kb2[n0 + onn];
        rgam = gamma[n0 + onn];
        rbet = beta[n0 + onn];
        rb4[0] = __ldg(&bi[n0 + onn]); rb4[1] = __ldg(&bf[n0 + onn]);
        rb4[2] = __ldg(&bc[n0 + onn]); rb4[3] = __ldg(&bo[n0 + onn]);
    }
    __syncthreads();
    // all mbarriers initialized cluster-wide before any arrive
    asm volatile("barrier.cluster.arrive.aligned;" ::: "memory");
    asm volatile("barrier.cluster.wait.aligned;"   ::: "memory");

    const float invH = 1.f / (float)H;

    // ---- t=0: stage x(0), xproj partials, xpv regs ----
    {
        int d0 = (tid & 63) * 2, bb = tid >> 6;
        const float* xrow = x + (size_t)(b0 + bb) * T * D;
        float2 v = __ldcg((const float2*)(xrow + d0));
        sX[d0 * 8 + bb] = v.x; sX[(d0 + 1) * 8 + bb] = v.y;
    }
    __syncthreads();
    {
        uint64_t A0 = 0, A1 = 0, A2 = 0, A3 = 0;
        const int db = xdp * 16;
#pragma unroll
        for (int i = 0; i < 16; i++) {
            int d = db + i;
            ulonglong2 xa = *(const ulonglong2*)&sX[d * 8];
            ulonglong2 xb = *(const ulonglong2*)&sX[d * 8 + 4];
            uint64_t W = pack2(sW[d * 64 + xc]);
            ffma2(A0, xa.x, W); ffma2(A1, xa.y, W);
            ffma2(A2, xb.x, W); ffma2(A3, xb.y, W);
        }
        float* dst = &sXP[(xdp * 64 + xc) * 8];
        float2 f0 = unpk(A0), f1 = unpk(A1), f2 = unpk(A2), f3 = unpk(A3);
        dst[0] = f0.x; dst[1] = f0.y; dst[2] = f1.x; dst[3] = f1.y;
        dst[4] = f2.x; dst[5] = f2.y; dst[6] = f3.x; dst[7] = f3.y;
    }
    __syncthreads();
    if (tid < 128) {
#pragma unroll
        for (int g = 0; g < 4; g++) {
            int q = onn * 4 + g;
            float v = rb4[g];
#pragma unroll
            for (int dp = 0; dp < 8; dp++) v += sXP[(dp * 64 + q) * 8 + obb];
            xpv[g] = v;
        }
    }
    __syncthreads();

    for (int t = 0; t < T; t++) {
        const uint32_t par = t & 1;
        float outv = 0.f;
        if (t > 0) {
            // ---- stage h ----
            {
                const float4* src = (const float4*)(g_h + bg * (H * BPG));
                *(float4*)&sAct[tid * 4] = __ldcg(&src[tid]);
            }
            __syncthreads();
            // ---- stats partials + P1 producer ----
            {
                float s = 0.f, s2 = 0.f;
#pragma unroll
                for (int j = 0; j < 4; j++) {
                    float v = sAct[tid + j * 512];
                    s += v; s2 += v * v;
                }
                s  += __shfl_xor_sync(0xffffffffu, s, 8);
                s2 += __shfl_xor_sync(0xffffffffu, s2, 8);
                s  += __shfl_xor_sync(0xffffffffu, s, 16);
                s2 += __shfl_xor_sync(0xffffffffu, s2, 16);
                int lane = tid & 31, wp = tid >> 5;
                if (lane < 8) { sSt[wp * 16 + lane * 2] = s; sSt[wp * 16 + lane * 2 + 1] = s2; }
            }
            {
                uint64_t A0 = 0, A1 = 0, A2 = 0, A3 = 0;
                const int kb = p1chunk * 32;
#pragma unroll
                for (int kk = 0; kk < 32; kk++) {
                    const float* hp = &sAct[(kb + kk) * 8];
                    ulonglong2 pa = *(const ulonglong2*)hp;
                    ulonglong2 pb = *(const ulonglong2*)(hp + 4);
                    uint64_t W = pack2(wU[kk]);
                    ffma2(A0, pa.x, W); ffma2(A1, pa.y, W);
                    ffma2(A2, pb.x, W); ffma2(A3, pb.y, W);
                }
                int base = p1chunk * 576 + p1q * 9;
                float2 f;
                f = unpk(A0); sRed[base + 0] = f.x; sRed[base + 1] = f.y;
                f = unpk(A1); sRed[base + 2] = f.x; sRed[base + 3] = f.y;
                f = unpk(A2); sRed[base + 4] = f.x; sRed[base + 5] = f.y;
                f = unpk(A3); sRed[base + 6] = f.x; sRed[base + 7] = f.y;
            }
            __syncthreads();
        }

        // ---- owner threads: LN finalize, gates, c update ----
        if (tid < 128) {
            float pre[4];
            if (t > 0) {
                float ss = 0.f, qq = 0.f;
#pragma unroll
                for (int w = 0; w < 16; w++) {
                    ss += sSt[w * 16 + obb * 2];
                    qq += sSt[w * 16 + obb * 2 + 1];
                }
                float mu = ss * invH;
                float var = qq * invH - mu * mu;
                float rs = rsqrtf(var + EPS);
                outv = (sAct[(n0 + onn) * 8 + obb] - mu) * rs * rgam + rbet;
#pragma unroll
                for (int g = 0; g < 4; g++) {
                    int q = onn * 4 + g;
                    float d = 0.f;
#pragma unroll
                    for (int c = 0; c < 8; c++) d += sRed[c * 576 + q * 9 + obb];
                    pre[g] = xpv[g] + rs * (d - mu * sGU[q]) + sBU[q];
                }
            } else {
#pragma unroll
                for (int g = 0; g < 4; g++) pre[g] = xpv[g];
            }
            float iv = fsig(pre[0]), fv = fsig(pre[1]);
            float ct = ftanh(pre[2]);
            oreg = fsig(pre[3]);
            creg = fv * creg + iv * ct;
            __stcg(&g_c[bg * (H * BPG) + (n0 + onn) * BPG + obb], creg);
            cl_arrive(mbC, 128, tid);     // barrier 1 arrive
        }
        if (t > 0 && tid < 128)
            out[((size_t)(b0 + obb) * T + (t - 1)) * H + n0 + onn] = outv;
        if (t + 1 < T) {                  // stage x(t+1)
            int d0 = (tid & 63) * 2, bb = tid >> 6;
            const float* xrow = x + (size_t)(b0 + bb) * T * D + (size_t)(t + 1) * D;
            float2 v = __ldcg((const float2*)(xrow + d0));
            sX[d0 * 8 + bb] = v.x; sX[(d0 + 1) * 8 + bb] = v.y;
        }
        cl_wait(mbC, par);                // barrier 1 wait (HW sleep)

        // ---- stage c ----
        {
            const float4* src = (const float4*)(g_c + bg * (H * BPG));
            *(float4*)&sAct[tid * 4] = __ldcg(&src[tid]);
        }
        __syncthreads();

        // ---- P2: z = tanh(c @ K1 + kb1) ----
        {
            uint64_t A0 = 0, A1 = 0, A2 = 0, A3 = 0;
            const int kb = p2chunk * 16;
#pragma unroll
            for (int kk = 0; kk < 16; kk++) {
                const float* cp = &sAct[(kb + kk) * 8];
                ulonglong2 pa = *(const ulonglong2*)cp;
                ulonglong2 pb = *(const ulonglong2*)(cp + 4);
                uint64_t W = pack2(wK1[kk]);
                ffma2(A0, pa.x, W); ffma2(A1, pa.y, W);
                ffma2(A2, pb.x, W); ffma2(A3, pb.y, W);
            }
            int base = p2chunk * 288 + p2m * 9;
            float2 f;
            f = unpk(A0); sRed[base + 0] = f.x; sRed[base + 1] = f.y;
            f = unpk(A1); sRed[base + 2] = f.x; sRed[base + 3] = f.y;
            f = unpk(A2); sRed[base + 4] = f.x; sRed[base + 5] = f.y;
            f = unpk(A3); sRed[base + 6] = f.x; sRed[base + 7] = f.y;
        }
        __syncthreads();
        if (tid < 256) {
            int mq = tid >> 3, bb = tid & 7;
            float d = 0.f;
#pragma unroll
            for (int c = 0; c < 16; c++) d += sRed[c * 288 + mq * 9 + bb];
            sZp[mq * 8 + (bb & 3) * 2 + (bb >> 2)] = ftanh(d + rkb1);
        }
        __syncthreads();

        // ---- P3 producer ----
        float2 f0, f1, f2, f3;
        {
            uint64_t A0 = 0, A1 = 0, A2 = 0, A3 = 0;
#pragma unroll
            for (int mm = 0; mm < 16; mm++) {
                const float* zp = &sZp[(p3mh * 16 + mm) * 8];
                ulonglong2 pa = *(const ulonglong2*)zp;
                ulonglong2 pb = *(const ulonglong2*)(zp + 4);
                uint64_t W = pack2(wK2[mm]);
                ffma2(A0, pa.x, W); ffma2(A1, pa.y, W);
                ffma2(A2, pb.x, W); ffma2(A3, pb.y, W);
            }
            f0 = unpk(A0); f1 = unpk(A1); f2 = unpk(A2); f3 = unpk(A3);
            if (p3mh == 1) {
                int base = p3n * 9;
                sRed[base + 0] = f0.x; sRed[base + 1] = f1.x; sRed[base + 2] = f2.x; sRed[base + 3] = f3.x;
                sRed[base + 4] = f0.y; sRed[base + 5] = f1.y; sRed[base + 6] = f2.y; sRed[base + 7] = f3.y;
            }
        }
        __syncthreads();
        if (tid < 256) {
            int base = p3n * 9;
            float4 lo = make_float4(f0.x + sRed[base + 0], f1.x + sRed[base + 1],
                                    f2.x + sRed[base + 2], f3.x + sRed[base + 3]);
            float4 hi = make_float4(f0.y + sRed[base + 4], f1.y + sRed[base + 5],
                                    f2.y + sRed[base + 6], f3.y + sRed[base + 7]);
            float* gp = &g_part[(((size_t)bg * 16 + cg) * H + p3n) * BPG];
            __stcg((float4*)gp, lo);
            __stcg((float4*)(gp + 4), hi);
            cl_arrive(mbP, 256, tid);     // barrier 2 arrive
        }
        if (t + 1 < T) {                  // xproj(t+1) in wait slack
            uint64_t A0 = 0, A1 = 0, A2 = 0, A3 = 0;
            const int db = xdp * 16;
#pragma unroll
            for (int i = 0; i < 16; i++) {
                int d = db + i;
                ulonglong2 xa = *(const ulonglong2*)&sX[d * 8];
                ulonglong2 xb = *(const ulonglong2*)&sX[d * 8 + 4];
                uint64_t W = pack2(sW[d * 64 + xc]);
                ffma2(A0, xa.x, W); ffma2(A1, xa.y, W);
                ffma2(A2, xb.x, W); ffma2(A3, xb.y, W);
            }
            float* dst = &sXP[(xdp * 64 + xc) * 8];
            float2 g0 = unpk(A0), g1 = unpk(A1), g2 = unpk(A2), g3 = unpk(A3);
            dst[0] = g0.x; dst[1] = g0.y; dst[2] = g1.x; dst[3] = g1.y;
            dst[4] = g2.x; dst[5] = g2.y; dst[6] = g3.x; dst[7] = g3.y;
        }
        cl_wait(mbP, par);                // barrier 2 wait
        __syncthreads();                  // orders sXP writes before xpv reads

        // ---- P3 consumer: owner reads 16 partials directly ----
        if (tid < 128) {
            float ssum = 0.f;
#pragma unroll
            for (int j = 0; j < 16; j++)
                ssum += __ldcg(&g_part[(((size_t)bg * 16 + j) * H + n0 + onn) * BPG + obb]);
            float hn = oreg * ftanh(ssum + rkb2);
            __stcg(&g_h[bg * (H * BPG) + (n0 + onn) * BPG + obb], hn);
            cl_arrive(mbH, 128, tid);     // barrier 3 arrive
        }
        if (t + 1 < T && tid < 128) {     // xpv regs in wait slack
#pragma unroll
            for (int g = 0; g < 4; g++) {
                int q = onn * 4 + g;
                float v = rb4[g];
#pragma unroll
                for (int dp = 0; dp < 8; dp++) v += sXP[(dp * 64 + q) * 8 + obb];
                xpv[g] = v;
            }
        }
        cl_wait(mbH, par);                // barrier 3 wait
    }

    // ---- epilogue: LN of h(T-1) ----
    {
        {
            const float4* src = (const float4*)(g_h + bg * (H * BPG));
            *(float4*)&sAct[tid * 4] = __ldcg(&src[tid]);
        }
        __syncthreads();
        {
            float s = 0.f, s2 = 0.f;
#pragma unroll
            for (int j = 0; j < 4; j++) {
                float v = sAct[tid + j * 512];
                s += v; s2 += v * v;
            }
            s  += __shfl_xor_sync(0xffffffffu, s, 8);
            s2 += __shfl_xor_sync(0xffffffffu, s2, 8);
            s  += __shfl_xor_sync(0xffffffffu, s, 16);
            s2 += __shfl_xor_sync(0xffffffffu, s2, 16);
            int lane = tid & 31, wp = tid >> 5;
            if (lane < 8) { sSt[wp * 16 + lane * 2] = s; sSt[wp * 16 + lane * 2 + 1] = s2; }
        }
        __syncthreads();
        if (tid < 128) {
            float ss = 0.f, qq = 0.f;
#pragma unroll
            for (int w = 0; w < 16; w++) {
                ss += sSt[w * 16 + obb * 2];
                qq += sSt[w * 16 + obb * 2 + 1];
            }
            float mu = ss * invH;
            float var = qq * invH - mu * mu;
            float rs = rsqrtf(var + EPS);
            float hr = sAct[(n0 + onn) * 8 + obb];
            float hn = (hr - mu) * rs * rgam + rbet;
            out[((size_t)(b0 + obb) * T + (T - 1)) * H + n0 + onn] = hn;
            if (has_hc) {
                out[(size_t)B * T * H + (size_t)(b0 + obb) * H + n0 + onn] = hn;
                out[(size_t)B * T * H + (size_t)B * H + (size_t)(b0 + obb) * H + n0 + onn] = creg;
            }
        }
    }
    // quiesce cluster before exit
    asm volatile("barrier.cluster.arrive.aligned;" ::: "memory");
    asm volatile("barrier.cluster.wait.aligned;"   ::: "memory");
}

// ---------------- launch ----------------
extern "C" void kernel_launch(void* const* d_in, const int* in_sizes, int n_in,
                              void* d_out, int out_size)
{
    const float* x  = (const float*)d_in[0];
    const float* Wi = (const float*)d_in[1];  const float* bi = (const float*)d_in[2];
    const float* Wf = (const float*)d_in[3];  const float* bf = (const float*)d_in[4];
    const float* Wc = (const float*)d_in[5];  const float* bc = (const float*)d_in[6];
    const float* Wo = (const float*)d_in[7];  const float* bo = (const float*)d_in[8];
    const float* Ui = (const float*)d_in[9];  const float* Uf = (const float*)d_in[10];
    const float* Uc = (const float*)d_in[11]; const float* Uo = (const float*)d_in[12];
    const float* K1 = (const float*)d_in[13]; const float* kb1 = (const float*)d_in[14];
    const float* K2 = (const float*)d_in[15]; const float* kb2 = (const float*)d_in[16];
    const float* gamma = (const float*)d_in[17];
    const float* beta  = (const float*)d_in[18];
    float* out = (float*)d_out;

    const int has_hc = (out_size >= B * T * H + 2 * B * H) ? 1 : 0;

    // actual smem use ~83KB; pad to 120KB to force 1 CTA/SM spread
    const int smem_scan = 120 * 1024;

    cudaFuncSetAttribute(k_scan, cudaFuncAttributeMaxDynamicSharedMemorySize, smem_scan);
    cudaFuncSetAttribute(k_scan, cudaFuncAttributeNonPortableClusterSizeAllowed, 1);

    k_init<<<1, 32>>>();
    k_dummy<<<1, 32>>>();
    k_dummy<<<1, 32>>>();

    cudaLaunchConfig_t cfg = {};
    cfg.gridDim = dim3(NCTA, 1, 1);
    cfg.blockDim = dim3(NT, 1, 1);
    cfg.dynamicSmemBytes = smem_scan;
    cfg.stream = 0;
    cudaLaunchAttribute attrs[1];
    attrs[0].id = cudaLaunchAttributeClusterDimension;
    attrs[0].val.clusterDim.x = CSZ;
    attrs[0].val.clusterDim.y = 1;
    attrs[0].val.clusterDim.z = 1;
    cfg.attrs = attrs;
    cfg.numAttrs = 1;
    cudaLaunchKernelEx(&cfg, k_scan, x, Wi, bi, Wf, bf, Wc, bc, Wo, bo,
                       Ui, Uf, Uc, Uo, K1, kb1, K2, kb2,
                       gamma, beta, out, has_hc);
}

// round 16
// speedup vs baseline: 1.7315x; 1.7315x over previous
#include <cuda_runtime.h>
#include <math.h>
#include <stdint.h>

constexpr int B  = 64;
constexpr int T  = 2048;
constexpr int D  = 128;
constexpr int H  = 256;
constexpr int H2 = 512;
constexpr float EPS = 1e-5f;

constexpr int NCTA = 128;   // 16 col-groups x 8 batch-groups
constexpr int NT   = 512;
constexpr int GR   = 8;
constexpr int BPG  = 8;

// ---------------- device scratch ----------------
__device__ float g_h[GR * H * BPG];
__device__ float g_c[GR * H * BPG];
__device__ float g_part[(size_t)GR * 16 * H * BPG];
__device__ unsigned int g_barr[GR * 32];

__global__ void k_init() { if (threadIdx.x < GR * 32) g_barr[threadIdx.x] = 0u; }
__global__ void k_dummy() { }

// ---------------- packed f32x2 helpers ----------------
__device__ __forceinline__ uint64_t pack2(float v) {
    uint64_t r;
    asm("mov.b64 %0, {%1, %1};" : "=l"(r) : "r"(__float_as_uint(v)));
    return r;
}
__device__ __forceinline__ void ffma2(uint64_t& a, uint64_t x, uint64_t y) {
    asm("fma.rn.f32x2 %0, %1, %2, %0;" : "+l"(a) : "l"(x), "l"(y));
}
__device__ __forceinline__ float2 unpk(uint64_t a) {
    float2 f;
    asm("mov.b64 {%0, %1}, %2;" : "=f"(f.x), "=f"(f.y) : "l"(a));
    return f;
}

// ---------------- fast transcendentals (safe saturation) ----------------
__device__ __forceinline__ float fsig(float v) {
    float e = __expf(-v);
    return __fdividef(1.f, 1.f + e);
}
__device__ __forceinline__ float ftanh(float v) {
    float e = __expf(-2.f * fabsf(v));
    float t = __fdividef(1.f - e, 1.f + e);
    return copysignf(t, v);
}

// ---------------- group barrier ----------------
// Sub-block arrive: only the producing warps rendezvous (named barrier 1),
// then tid0 releases. Consumers are ordered by the full __syncthreads in
// gsync_wait before they touch exchanged data.
__device__ __forceinline__ void gsync_arrive_n(int bg, int nthr)
{
    asm volatile("bar.sync 1, %0;" :: "r"(nthr) : "memory");
    if (threadIdx.x == 0)
        asm volatile("red.release.gpu.global.add.u32 [%0], 1;"
                     :: "l"(&g_barr[bg * 32]) : "memory");
}
__device__ __forceinline__ void gsync_wait(int bg, unsigned int tgt)
{
    if (threadIdx.x < 32) {
        unsigned int v;
        do {
            asm volatile("ld.acquire.gpu.global.u32 %0, [%1];"
                         : "=r"(v) : "l"(&g_barr[bg * 32]) : "memory");
        } while (v < tgt);
    }
    __syncthreads();
}

// ---------------- persistent scan, fused input projection ----------------
__global__ void __launch_bounds__(NT, 1) k_scan(
    const float* __restrict__ x,
    const float* __restrict__ Wi, const float* __restrict__ bi,
    const float* __restrict__ Wf, const float* __restrict__ bf,
    const float* __restrict__ Wc, const float* __restrict__ bc,
    const float* __restrict__ Wo, const float* __restrict__ bo,
    const float* __restrict__ Ui, const float* __restrict__ Uf,
    const float* __restrict__ Uc, const float* __restrict__ Uo,
    const float* __restrict__ K1, const float* __restrict__ kb1,
    const float* __restrict__ K2, const float* __restrict__ kb2,
    const float* __restrict__ gamma, const float* __restrict__ beta,
    float* __restrict__ out, int has_hc)
{
    extern __shared__ float sm[];
    float* sAct = sm;             // 2048 activation staging [k*8+b]
    float* sRed = sAct + 2048;    // 4608 split-K partials
    float* sZp  = sRed + 4608;    //  256 z pair-interleaved [m'][8]
    float* sGU  = sZp + 256;      //   64
    float* sBU  = sGU + 64;       //   64
    float* sSt  = sBU + 64;       //  256 stats partials [16w][8b][2]
    float* sW   = sSt + 256;      // 8192 W slice [d][n'*4+g]
    float* sX   = sW  + 8192;     // 1024 x tile [d*8+b]
    float* sXP  = sX  + 1024;     // 4096 xproj partials [(dp*64+q)*8+b]

    const int tid = threadIdx.x;
    const int cta = blockIdx.x;
    const int cg  = cta & 15;
    const int bg  = cta >> 4;
    const int n0  = cg * 16;
    const int m0  = cg * 32;
    const int b0  = bg * 8;

    // producer roles
    const int p1q     = tid & 63;
    const int p1n     = p1q >> 2;
    const int p1g     = p1q & 3;
    const int p1chunk = tid >> 6;          // 8 x 32k
    const int p2m     = tid & 31;
    const int p2chunk = tid >> 5;          // 16 x 16k
    const int p3n     = tid & 255;
    const int p3mh    = tid >> 8;
    // owner role (idx<128)
    const int onn = tid >> 3;
    const int obb = tid & 7;
    // xproj producer role
    const int xc  = tid & 63;
    const int xdp = tid >> 6;

    // ---- weights into registers ----
    float wU[32], wK1[16], wK2[16];
    {
        const float* Up = (p1g == 0) ? Ui : (p1g == 1) ? Uf : (p1g == 2) ? Uc : Uo;
#pragma unroll
        for (int kk = 0; kk < 32; kk++) {
            int k = p1chunk * 32 + kk;
            wU[kk] = __ldg(&gamma[k]) * __ldg(&Up[(size_t)k * H + n0 + p1n]);
        }
#pragma unroll
        for (int kk = 0; kk < 16; kk++) {
            int k = p2chunk * 16 + kk;
            wK1[kk] = __ldg(&K1[(size_t)k * H2 + m0 + p2m]);
        }
#pragma unroll
        for (int mm = 0; mm < 16; mm++) {
            int m = m0 + p3mh * 16 + mm;
            wK2[mm] = __ldg(&K2[(size_t)m * H + p3n]);
        }
    }

    // ---- W slice into smem ----
    for (int idx = tid; idx < D * 64; idx += NT) {
        int d = idx >> 6, q = idx & 63, n = q >> 2, g = q & 3;
        const float* Wp = (g == 0) ? Wi : (g == 1) ? Wf : (g == 2) ? Wc : Wo;
        sW[idx] = __ldg(&Wp[(size_t)d * H + n0 + n]);
    }

    if (tid < 64) {
        int n = tid >> 2, g = tid & 3;
        const float* Up = (g == 0) ? Ui : (g == 1) ? Uf : (g == 2) ? Uc : Uo;
        float s = 0.f, bs = 0.f;
        for (int k = 0; k < H; k++) {
            float u = __ldg(&Up[(size_t)k * H + n0 + n]);
            s  += __ldg(&gamma[k]) * u;
            bs += __ldg(&beta[k])  * u;
        }
        sGU[tid] = s; sBU[tid] = bs;
    }
    float rkb1 = 0.f;
    if (tid < 256) rkb1 = kb1[m0 + (tid >> 3)];

    // owner-thread constants + state
    float rkb2 = 0.f, rgam = 0.f, rbet = 0.f, rb4[4];
    float creg = 0.f, oreg = 0.f, xpv[4] = {0.f, 0.f, 0.f, 0.f};
    if (tid < 128) {
        rkb2 = kb2[n0 + onn];
        rgam = gamma[n0 + onn];
        rbet = beta[n0 + onn];
        rb4[0] = __ldg(&bi[n0 + onn]); rb4[1] = __ldg(&bf[n0 + onn]);
        rb4[2] = __ldg(&bc[n0 + onn]); rb4[3] = __ldg(&bo[n0 + onn]);
    }
    __syncthreads();

    unsigned int tgt = 0;
    const float invH = 1.f / (float)H;

    // ---- t=0: stage x(0), xproj partials, xpv regs ----
    {
        int d0 = (tid & 63) * 2, bb = tid >> 6;
        const float* xrow = x + (size_t)(b0 + bb) * T * D;
        float2 v = __ldcg((const float2*)(xrow + d0));
        sX[d0 * 8 + bb] = v.x; sX[(d0 + 1) * 8 + bb] = v.y;
    }
    __syncthreads();
    {
        uint64_t A0 = 0, A1 = 0, A2 = 0, A3 = 0;
        const int db = xdp * 16;
#pragma unroll
        for (int i = 0; i < 16; i++) {
            int d = db + i;
            ulonglong2 xa = *(const ulonglong2*)&sX[d * 8];
            ulonglong2 xb = *(const ulonglong2*)&sX[d * 8 + 4];
            uint64_t W = pack2(sW[d * 64 + xc]);
            ffma2(A0, xa.x, W); ffma2(A1, xa.y, W);
            ffma2(A2, xb.x, W); ffma2(A3, xb.y, W);
        }
        float* dst = &sXP[(xdp * 64 + xc) * 8];
        float2 f0 = unpk(A0), f1 = unpk(A1), f2 = unpk(A2), f3 = unpk(A3);
        dst[0] = f0.x; dst[1] = f0.y; dst[2] = f1.x; dst[3] = f1.y;
        dst[4] = f2.x; dst[5] = f2.y; dst[6] = f3.x; dst[7] = f3.y;
    }
    __syncthreads();
    if (tid < 128) {
#pragma unroll
        for (int g = 0; g < 4; g++) {
            int q = onn * 4 + g;
            float v = rb4[g];
#pragma unroll
            for (int dp = 0; dp < 8; dp++) v += sXP[(dp * 64 + q) * 8 + obb];
            xpv[g] = v;
        }
    }
    __syncthreads();

    for (int t = 0; t < T; t++) {
        float outv = 0.f;
        if (t > 0) {
            // ---- stage h ----
            {
                const float4* src = (const float4*)(g_h + bg * (H * BPG));
                *(float4*)&sAct[tid * 4] = __ldcg(&src[tid]);
            }
            __syncthreads();
            // ---- stats partials + P1 producer ----
            {
                float s = 0.f, s2 = 0.f;
#pragma unroll
                for (int j = 0; j < 4; j++) {
                    float v = sAct[tid + j * 512];
                    s += v; s2 += v * v;
                }
                s  += __shfl_xor_sync(0xffffffffu, s, 8);
                s2 += __shfl_xor_sync(0xffffffffu, s2, 8);
                s  += __shfl_xor_sync(0xffffffffu, s, 16);
                s2 += __shfl_xor_sync(0xffffffffu, s2, 16);
                int lane = tid & 31, wp = tid >> 5;
                if (lane < 8) { sSt[wp * 16 + lane * 2] = s; sSt[wp * 16 + lane * 2 + 1] = s2; }
            }
            {
                uint64_t A0 = 0, A1 = 0, A2 = 0, A3 = 0;
                const int kb = p1chunk * 32;
#pragma unroll
                for (int kk = 0; kk < 32; kk++) {
                    const float* hp = &sAct[(kb + kk) * 8];
                    ulonglong2 pa = *(const ulonglong2*)hp;
                    ulonglong2 pb = *(const ulonglong2*)(hp + 4);
                    uint64_t W = pack2(wU[kk]);
                    ffma2(A0, pa.x, W); ffma2(A1, pa.y, W);
                    ffma2(A2, pb.x, W); ffma2(A3, pb.y, W);
                }
                int base = p1chunk * 576 + p1q * 9;
                float2 f;
                f = unpk(A0); sRed[base + 0] = f.x; sRed[base + 1] = f.y;
                f = unpk(A1); sRed[base + 2] = f.x; sRed[base + 3] = f.y;
                f = unpk(A2); sRed[base + 4] = f.x; sRed[base + 5] = f.y;
                f = unpk(A3); sRed[base + 6] = f.x; sRed[base + 7] = f.y;
            }
            __syncthreads();
        }

        // ---- owner threads: LN finalize, gates, c update ----
        if (tid < 128) {
            float pre[4];
            if (t > 0) {
                float ss = 0.f, qq = 0.f;
#pragma unroll
                for (int w = 0; w < 16; w++) {
                    ss += sSt[w * 16 + obb * 2];
                    qq += sSt[w * 16 + obb * 2 + 1];
                }
                float mu = ss * invH;
                float var = qq * invH - mu * mu;
                float rs = rsqrtf(var + EPS);
                outv = (sAct[(n0 + onn) * 8 + obb] - mu) * rs * rgam + rbet;
#pragma unroll
                for (int g = 0; g < 4; g++) {
                    int q = onn * 4 + g;
                    float d = 0.f;
#pragma unroll
                    for (int c = 0; c < 8; c++) d += sRed[c * 576 + q * 9 + obb];
                    pre[g] = xpv[g] + rs * (d - mu * sGU[q]) + sBU[q];
                }
            } else {
#pragma unroll
                for (int g = 0; g < 4; g++) pre[g] = xpv[g];
            }
            float iv = fsig(pre[0]), fv = fsig(pre[1]);
            float ct = ftanh(pre[2]);
            oreg = fsig(pre[3]);
            creg = fv * creg + iv * ct;
            __stcg(&g_c[bg * (H * BPG) + (n0 + onn) * BPG + obb], creg);
            gsync_arrive_n(bg, 128);      // barrier 1 arrive: producers only
        }
        if (t > 0 && tid < 128)
            out[((size_t)(b0 + obb) * T + (t - 1)) * H + n0 + onn] = outv;
        if (t + 1 < T) {                  // stage x(t+1)
            int d0 = (tid & 63) * 2, bb = tid >> 6;
            const float* xrow = x + (size_t)(b0 + bb) * T * D + (size_t)(t + 1) * D;
            float2 v = __ldcg((const float2*)(xrow + d0));
            sX[d0 * 8 + bb] = v.x; sX[(d0 + 1) * 8 + bb] = v.y;
        }
        tgt += 16;
        gsync_wait(bg, tgt);

        // ---- stage c ----
        {
            const float4* src = (const float4*)(g_c + bg * (H * BPG));
            *(float4*)&sAct[tid * 4] = __ldcg(&src[tid]);
        }
        __syncthreads();

        // ---- P2: z = tanh(c @ K1 + kb1) ----
        {
            uint64_t A0 = 0, A1 = 0, A2 = 0, A3 = 0;
            const int kb = p2chunk * 16;
#pragma unroll
            for (int kk = 0; kk < 16; kk++) {
                const float* cp = &sAct[(kb + kk) * 8];
                ulonglong2 pa = *(const ulonglong2*)cp;
                ulonglong2 pb = *(const ulonglong2*)(cp + 4);
                uint64_t W = pack2(wK1[kk]);
                ffma2(A0, pa.x, W); ffma2(A1, pa.y, W);
                ffma2(A2, pb.x, W); ffma2(A3, pb.y, W);
            }
            int base = p2chunk * 288 + p2m * 9;
            float2 f;
            f = unpk(A0); sRed[base + 0] = f.x; sRed[base + 1] = f.y;
            f = unpk(A1); sRed[base + 2] = f.x; sRed[base + 3] = f.y;
            f = unpk(A2); sRed[base + 4] = f.x; sRed[base + 5] = f.y;
            f = unpk(A3); sRed[base + 6] = f.x; sRed[base + 7] = f.y;
        }
        __syncthreads();
        if (tid < 256) {
            int mq = tid >> 3, bb = tid & 7;
            float d = 0.f;
#pragma unroll
            for (int c = 0; c < 16; c++) d += sRed[c * 288 + mq * 9 + bb];
            sZp[mq * 8 + (bb & 3) * 2 + (bb >> 2)] = ftanh(d + rkb1);
        }
        __syncthreads();

        // ---- P3 producer ----
        float2 f0, f1, f2, f3;
        {
            uint64_t A0 = 0, A1 = 0, A2 = 0, A3 = 0;
#pragma unroll
            for (int mm = 0; mm < 16; mm++) {
                const float* zp = &sZp[(p3mh * 16 + mm) * 8];
                ulonglong2 pa = *(const ulonglong2*)zp;
                ulonglong2 pb = *(const ulonglong2*)(zp + 4);
                uint64_t W = pack2(wK2[mm]);
                ffma2(A0, pa.x, W); ffma2(A1, pa.y, W);
                ffma2(A2, pb.x, W); ffma2(A3, pb.y, W);
            }
            f0 = unpk(A0); f1 = unpk(A1); f2 = unpk(A2); f3 = unpk(A3);
            if (p3mh == 1) {
                int base = p3n * 9;
                sRed[base + 0] = f0.x; sRed[base + 1] = f1.x; sRed[base + 2] = f2.x; sRed[base + 3] = f3.x;
                sRed[base + 4] = f0.y; sRed[base + 5] = f1.y; sRed[base + 6] = f2.y; sRed[base + 7] = f3.y;
            }
        }
        __syncthreads();
        if (tid < 256) {
            int base = p3n * 9;
            float4 lo = make_float4(f0.x + sRed[base + 0], f1.x + sRed[base + 1],
                                    f2.x + sRed[base + 2], f3.x + sRed[base + 3]);
            float4 hi = make_float4(f0.y + sRed[base + 4], f1.y + sRed[base + 5],
                                    f2.y + sRed[base + 6], f3.y + sRed[base + 7]);
            float* gp = &g_part[(((size_t)bg * 16 + cg) * H + p3n) * BPG];
            __stcg((float4*)gp, lo);
            __stcg((float4*)(gp + 4), hi);
            gsync_arrive_n(bg, 256);      // barrier 2 arrive: producers only
        }
        if (t + 1 < T) {                  // xproj(t+1) in wait slack
            uint64_t A0 = 0, A1 = 0, A2 = 0, A3 = 0;
            const int db = xdp * 16;
#pragma unroll
            for (int i = 0; i < 16; i++) {
                int d = db + i;
                ulonglong2 xa = *(const ulonglong2*)&sX[d * 8];
                ulonglong2 xb = *(const ulonglong2*)&sX[d * 8 + 4];
                uint64_t W = pack2(sW[d * 64 + xc]);
                ffma2(A0, xa.x, W); ffma2(A1, xa.y, W);
                ffma2(A2, xb.x, W); ffma2(A3, xb.y, W);
            }
            float* dst = &sXP[(xdp * 64 + xc) * 8];
            float2 g0 = unpk(A0), g1 = unpk(A1), g2 = unpk(A2), g3 = unpk(A3);
            dst[0] = g0.x; dst[1] = g0.y; dst[2] = g1.x; dst[3] = g1.y;
            dst[4] = g2.x; dst[5] = g2.y; dst[6] = g3.x; dst[7] = g3.y;
        }
        tgt += 16;
        gsync_wait(bg, tgt);

        // ---- P3 consumer: owner reads 16 partials directly ----
        if (tid < 128) {
            float ssum = 0.f;
#pragma unroll
            for (int j = 0; j < 16; j++)
                ssum += __ldcg(&g_part[(((size_t)bg * 16 + j) * H + n0 + onn) * BPG + obb]);
            float hn = oreg * ftanh(ssum + rkb2);
            __stcg(&g_h[bg * (H * BPG) + (n0 + onn) * BPG + obb], hn);
            gsync_arrive_n(bg, 128);      // barrier 3 arrive: producers only
        }
        if (t + 1 < T && tid < 128) {     // xpv regs in wait slack
#pragma unroll
            for (int g = 0; g < 4; g++) {
                int q = onn * 4 + g;
                float v = rb4[g];
#pragma unroll
                for (int dp = 0; dp < 8; dp++) v += sXP[(dp * 64 + q) * 8 + obb];
                xpv[g] = v;
            }
        }
        tgt += 16;
        gsync_wait(bg, tgt);
    }

    // ---- epilogue: LN of h(T-1) ----
    {
        {
            const float4* src = (const float4*)(g_h + bg * (H * BPG));
            *(float4*)&sAct[tid * 4] = __ldcg(&src[tid]);
        }
        __syncthreads();
        {
            float s = 0.f, s2 = 0.f;
#pragma unroll
            for (int j = 0; j < 4; j++) {
                float v = sAct[tid + j * 512];
                s += v; s2 += v * v;
            }
            s  += __shfl_xor_sync(0xffffffffu, s, 8);
            s2 += __shfl_xor_sync(0xffffffffu, s2, 8);
            s  += __shfl_xor_sync(0xffffffffu, s, 16);
            s2 += __shfl_xor_sync(0xffffffffu, s2, 16);
            int lane = tid & 31, wp = tid >> 5;
            if (lane < 8) { sSt[wp * 16 + lane * 2] = s; sSt[wp * 16 + lane * 2 + 1] = s2; }
        }
        __syncthreads();
        if (tid < 128) {
            float ss = 0.f, qq = 0.f;
#pragma unroll
            for (int w = 0; w < 16; w++) {
                ss += sSt[w * 16 + obb * 2];
                qq += sSt[w * 16 + obb * 2 + 1];
            }
            float mu = ss * invH;
            float var = qq * invH - mu * mu;
            float rs = rsqrtf(var + EPS);
            float hr = sAct[(n0 + onn) * 8 + obb];
            float hn = (hr - mu) * rs * rgam + rbet;
            out[((size_t)(b0 + obb) * T + (T - 1)) * H + n0 + onn] = hn;
            if (has_hc) {
                out[(size_t)B * T * H + (size_t)(b0 + obb) * H + n0 + onn] = hn;
                out[(size_t)B * T * H + (size_t)B * H + (size_t)(b0 + obb) * H + n0 + onn] = creg;
            }
        }
    }
}

// ---------------- launch ----------------
extern "C" void kernel_launch(void* const* d_in, const int* in_sizes, int n_in,
                              void* d_out, int out_size)
{
    const float* x  = (const float*)d_in[0];
    const float* Wi = (const float*)d_in[1];  const float* bi = (const float*)d_in[2];
    const float* Wf = (const float*)d_in[3];  const float* bf = (const float*)d_in[4];
    const float* Wc = (const float*)d_in[5];  const float* bc = (const float*)d_in[6];
    const float* Wo = (const float*)d_in[7];  const float* bo = (const float*)d_in[8];
    const float* Ui = (const float*)d_in[9];  const float* Uf = (const float*)d_in[10];
    const float* Uc = (const float*)d_in[11]; const float* Uo = (const float*)d_in[12];
    const float* K1 = (const float*)d_in[13]; const float* kb1 = (const float*)d_in[14];
    const float* K2 = (const float*)d_in[15]; const float* kb2 = (const float*)d_in[16];
    const float* gamma = (const float*)d_in[17];
    const float* beta  = (const float*)d_in[18];
    float* out = (float*)d_out;

    const int has_hc = (out_size >= B * T * H + 2 * B * H) ? 1 : 0;

    // actual smem use ~83KB; pad to 120KB to force 1 CTA/SM spread
    const int smem_scan = 120 * 1024;

    cudaFuncSetAttribute(k_scan, cudaFuncAttributeMaxDynamicSharedMemorySize, smem_scan);

    k_init<<<1, 512>>>();
    k_dummy<<<1, 32>>>();
    k_dummy<<<1, 32>>>();
    k_scan<<<NCTA, NT, smem_scan>>>(x, Wi, bi, Wf, bf, Wc, bc, Wo, bo,
                                    Ui, Uf, Uc, Uo, K1, kb1, K2, kb2,
                                    gamma, beta, out, has_hc);
}

// round 17
// speedup vs baseline: 1.7343x; 1.0016x over previous
#include <cuda_runtime.h>
#include <math.h>
#include <stdint.h>

constexpr int B  = 64;
constexpr int T  = 2048;
constexpr int D  = 128;
constexpr int H  = 256;
constexpr int H2 = 512;
constexpr float EPS = 1e-5f;

constexpr int NCTA = 128;   // 16 col-groups x 8 batch-groups
constexpr int NT   = 512;
constexpr int GR   = 8;
constexpr int BPG  = 8;

// ---------------- device scratch ----------------
__device__ float g_h[GR * H * BPG];
__device__ float g_c[GR * H * BPG];
__device__ float g_part[(size_t)GR * 16 * H * BPG];
__device__ unsigned int g_barr[GR * 32];

__global__ void k_init() { if (threadIdx.x < GR * 32) g_barr[threadIdx.x] = 0u; }
__global__ void k_dummy() { }

// ---------------- packed f32x2 helpers ----------------
__device__ __forceinline__ uint64_t pack2(float v) {
    uint64_t r;
    asm("mov.b64 %0, {%1, %1};" : "=l"(r) : "r"(__float_as_uint(v)));
    return r;
}
__device__ __forceinline__ void ffma2(uint64_t& a, uint64_t x, uint64_t y) {
    asm("fma.rn.f32x2 %0, %1, %2, %0;" : "+l"(a) : "l"(x), "l"(y));
}
__device__ __forceinline__ float2 unpk(uint64_t a) {
    float2 f;
    asm("mov.b64 {%0, %1}, %2;" : "=f"(f.x), "=f"(f.y) : "l"(a));
    return f;
}

// ---------------- fast transcendentals (safe saturation) ----------------
__device__ __forceinline__ float fsig(float v) {
    float e = __expf(-v);
    return __fdividef(1.f, 1.f + e);
}
__device__ __forceinline__ float ftanh(float v) {
    float e = __expf(-2.f * fabsf(v));
    float t = __fdividef(1.f - e, 1.f + e);
    return copysignf(t, v);
}

// ---------------- group barrier ----------------
// Sub-block arrive: only the producing warps rendezvous (named barrier 1),
// then tid0 releases.
__device__ __forceinline__ void gsync_arrive_n(int bg, int nthr)
{
    asm volatile("bar.sync 1, %0;" :: "r"(nthr) : "memory");
    if (threadIdx.x == 0)
        asm volatile("red.release.gpu.global.add.u32 [%0], 1;"
                     :: "l"(&g_barr[bg * 32]) : "memory");
}
// All warps poll independently (read-only, one L2 line) — each warp wakes on
// its own acquire load; no trailing __syncthreads. Cross-warp smem hazards at
// the exit are covered either by the own-CTA-arrival ordering (our release
// fires only after the producing warps' named bar) or by explicit syncs at
// the use sites.
__device__ __forceinline__ void gsync_wait_all(int bg, unsigned int tgt)
{
    unsigned int v;
    do {
        asm volatile("ld.acquire.gpu.global.u32 %0, [%1];"
                     : "=r"(v) : "l"(&g_barr[bg * 32]) : "memory");
    } while (v < tgt);
}

// ---------------- persistent scan, fused input projection ----------------
__global__ void __launch_bounds__(NT, 1) k_scan(
    const float* __restrict__ x,
    const float* __restrict__ Wi, const float* __restrict__ bi,
    const float* __restrict__ Wf, const float* __restrict__ bf,
    const float* __restrict__ Wc, const float* __restrict__ bc,
    const float* __restrict__ Wo, const float* __restrict__ bo,
    const float* __restrict__ Ui, const float* __restrict__ Uf,
    const float* __restrict__ Uc, const float* __restrict__ Uo,
    const float* __restrict__ K1, const float* __restrict__ kb1,
    const float* __restrict__ K2, const float* __restrict__ kb2,
    const float* __restrict__ gamma, const float* __restrict__ beta,
    float* __restrict__ out, int has_hc)
{
    extern __shared__ float sm[];
    float* sAct = sm;             // 2048 activation staging [k*8+b]
    float* sRed = sAct + 2048;    // 4608 split-K partials
    float* sZp  = sRed + 4608;    //  256 z pair-interleaved [m'][8]
    float* sGU  = sZp + 256;      //   64
    float* sBU  = sGU + 64;       //   64
    float* sSt  = sBU + 64;       //  256 stats partials [16w][8b][2]
    float* sW   = sSt + 256;      // 8192 W slice [d][n'*4+g]
    float* sX   = sW  + 8192;     // 1024 x tile [d*8+b]
    float* sXP  = sX  + 1024;     // 4096 xproj partials [(dp*64+q)*8+b]

    const int tid = threadIdx.x;
    const int cta = blockIdx.x;
    const int cg  = cta & 15;
    const int bg  = cta >> 4;
    const int n0  = cg * 16;
    const int m0  = cg * 32;
    const int b0  = bg * 8;

    // producer roles
    const int p1q     = tid & 63;
    const int p1n     = p1q >> 2;
    const int p1g     = p1q & 3;
    const int p1chunk = tid >> 6;          // 8 x 32k
    const int p2m     = tid & 31;
    const int p2chunk = tid >> 5;          // 16 x 16k
    const int p3n     = tid & 255;
    const int p3mh    = tid >> 8;
    // owner role (idx<128)
    const int onn = tid >> 3;
    const int obb = tid & 7;
    // xproj producer role
    const int xc  = tid & 63;
    const int xdp = tid >> 6;

    // ---- weights into registers ----
    float wU[32], wK1[16], wK2[16];
    {
        const float* Up = (p1g == 0) ? Ui : (p1g == 1) ? Uf : (p1g == 2) ? Uc : Uo;
#pragma unroll
        for (int kk = 0; kk < 32; kk++) {
            int k = p1chunk * 32 + kk;
            wU[kk] = __ldg(&gamma[k]) * __ldg(&Up[(size_t)k * H + n0 + p1n]);
        }
#pragma unroll
        for (int kk = 0; kk < 16; kk++) {
            int k = p2chunk * 16 + kk;
            wK1[kk] = __ldg(&K1[(size_t)k * H2 + m0 + p2m]);
        }
#pragma unroll
        for (int mm = 0; mm < 16; mm++) {
            int m = m0 + p3mh * 16 + mm;
            wK2[mm] = __ldg(&K2[(size_t)m * H + p3n]);
        }
    }

    // ---- W slice into smem ----
    for (int idx = tid; idx < D * 64; idx += NT) {
        int d = idx >> 6, q = idx & 63, n = q >> 2, g = q & 3;
        const float* Wp = (g == 0) ? Wi : (g == 1) ? Wf : (g == 2) ? Wc : Wo;
        sW[idx] = __ldg(&Wp[(size_t)d * H + n0 + n]);
    }

    if (tid < 64) {
        int n = tid >> 2, g = tid & 3;
        const float* Up = (g == 0) ? Ui : (g == 1) ? Uf : (g == 2) ? Uc : Uo;
        float s = 0.f, bs = 0.f;
        for (int k = 0; k < H; k++) {
            float u = __ldg(&Up[(size_t)k * H + n0 + n]);
            s  += __ldg(&gamma[k]) * u;
            bs += __ldg(&beta[k])  * u;
        }
        sGU[tid] = s; sBU[tid] = bs;
    }
    float rkb1 = 0.f;
    if (tid < 256) rkb1 = kb1[m0 + (tid >> 3)];

    // owner-thread constants + state
    float rkb2 = 0.f, rgam = 0.f, rbet = 0.f, rb4[4];
    float creg = 0.f, oreg = 0.f, xpv[4] = {0.f, 0.f, 0.f, 0.f};
    if (tid < 128) {
        rkb2 = kb2[n0 + onn];
        rgam = gamma[n0 + onn];
        rbet = beta[n0 + onn];
        rb4[0] = __ldg(&bi[n0 + onn]); rb4[1] = __ldg(&bf[n0 + onn]);
        rb4[2] = __ldg(&bc[n0 + onn]); rb4[3] = __ldg(&bo[n0 + onn]);
    }
    __syncthreads();

    unsigned int tgt = 0;
    const float invH = 1.f / (float)H;

    // ---- t=0: stage x(0), xproj partials, xpv regs ----
    {
        int d0 = (tid & 63) * 2, bb = tid >> 6;
        const float* xrow = x + (size_t)(b0 + bb) * T * D;
        float2 v = __ldcg((const float2*)(xrow + d0));
        sX[d0 * 8 + bb] = v.x; sX[(d0 + 1) * 8 + bb] = v.y;
    }
    __syncthreads();
    {
        uint64_t A0 = 0, A1 = 0, A2 = 0, A3 = 0;
        const int db = xdp * 16;
#pragma unroll
        for (int i = 0; i < 16; i++) {
            int d = db + i;
            ulonglong2 xa = *(const ulonglong2*)&sX[d * 8];
            ulonglong2 xb = *(const ulonglong2*)&sX[d * 8 + 4];
            uint64_t W = pack2(sW[d * 64 + xc]);
            ffma2(A0, xa.x, W); ffma2(A1, xa.y, W);
            ffma2(A2, xb.x, W); ffma2(A3, xb.y, W);
        }
        float* dst = &sXP[(xdp * 64 + xc) * 8];
        float2 f0 = unpk(A0), f1 = unpk(A1), f2 = unpk(A2), f3 = unpk(A3);
        dst[0] = f0.x; dst[1] = f0.y; dst[2] = f1.x; dst[3] = f1.y;
        dst[4] = f2.x; dst[5] = f2.y; dst[6] = f3.x; dst[7] = f3.y;
    }
    __syncthreads();
    if (tid < 128) {
#pragma unroll
        for (int g = 0; g < 4; g++) {
            int q = onn * 4 + g;
            float v = rb4[g];
#pragma unroll
            for (int dp = 0; dp < 8; dp++) v += sXP[(dp * 64 + q) * 8 + obb];
            xpv[g] = v;
        }
    }
    __syncthreads();

    for (int t = 0; t < T; t++) {
        float outv = 0.f;
        if (t > 0) {
            // ---- stage h ----
            {
                const float4* src = (const float4*)(g_h + bg * (H * BPG));
                *(float4*)&sAct[tid * 4] = __ldcg(&src[tid]);
            }
            __syncthreads();
            // ---- stats partials + P1 producer ----
            {
                float s = 0.f, s2 = 0.f;
#pragma unroll
                for (int j = 0; j < 4; j++) {
                    float v = sAct[tid + j * 512];
                    s += v; s2 += v * v;
                }
                s  += __shfl_xor_sync(0xffffffffu, s, 8);
                s2 += __shfl_xor_sync(0xffffffffu, s2, 8);
                s  += __shfl_xor_sync(0xffffffffu, s, 16);
                s2 += __shfl_xor_sync(0xffffffffu, s2, 16);
                int lane = tid & 31, wp = tid >> 5;
                if (lane < 8) { sSt[wp * 16 + lane * 2] = s; sSt[wp * 16 + lane * 2 + 1] = s2; }
            }
            {
                uint64_t A0 = 0, A1 = 0, A2 = 0, A3 = 0;
                const int kb = p1chunk * 32;
#pragma unroll
                for (int kk = 0; kk < 32; kk++) {
                    const float* hp = &sAct[(kb + kk) * 8];
                    ulonglong2 pa = *(const ulonglong2*)hp;
                    ulonglong2 pb = *(const ulonglong2*)(hp + 4);
                    uint64_t W = pack2(wU[kk]);
                    ffma2(A0, pa.x, W); ffma2(A1, pa.y, W);
                    ffma2(A2, pb.x, W); ffma2(A3, pb.y, W);
                }
                int base = p1chunk * 576 + p1q * 9;
                float2 f;
                f = unpk(A0); sRed[base + 0] = f.x; sRed[base + 1] = f.y;
                f = unpk(A1); sRed[base + 2] = f.x; sRed[base + 3] = f.y;
                f = unpk(A2); sRed[base + 4] = f.x; sRed[base + 5] = f.y;
                f = unpk(A3); sRed[base + 6] = f.x; sRed[base + 7] = f.y;
            }
            __syncthreads();
        }

        // ---- owner threads: LN finalize, gates, c update ----
        if (tid < 128) {
            float pre[4];
            if (t > 0) {
                float ss = 0.f, qq = 0.f;
#pragma unroll
                for (int w = 0; w < 16; w++) {
                    ss += sSt[w * 16 + obb * 2];
                    qq += sSt[w * 16 + obb * 2 + 1];
                }
                float mu = ss * invH;
                float var = qq * invH - mu * mu;
                float rs = rsqrtf(var + EPS);
                outv = (sAct[(n0 + onn) * 8 + obb] - mu) * rs * rgam + rbet;
#pragma unroll
                for (int g = 0; g < 4; g++) {
                    int q = onn * 4 + g;
                    float d = 0.f;
#pragma unroll
                    for (int c = 0; c < 8; c++) d += sRed[c * 576 + q * 9 + obb];
                    pre[g] = xpv[g] + rs * (d - mu * sGU[q]) + sBU[q];
                }
            } else {
#pragma unroll
                for (int g = 0; g < 4; g++) pre[g] = xpv[g];
            }
            float iv = fsig(pre[0]), fv = fsig(pre[1]);
            float ct = ftanh(pre[2]);
            oreg = fsig(pre[3]);
            creg = fv * creg + iv * ct;
            __stcg(&g_c[bg * (H * BPG) + (n0 + onn) * BPG + obb], creg);
            gsync_arrive_n(bg, 128);      // barrier 1 arrive: producers only
        }
        if (t > 0 && tid < 128)
            out[((size_t)(b0 + obb) * T + (t - 1)) * H + n0 + onn] = outv;
        if (t + 1 < T) {                  // stage x(t+1)
            int d0 = (tid & 63) * 2, bb = tid >> 6;
            const float* xrow = x + (size_t)(b0 + bb) * T * D + (size_t)(t + 1) * D;
            float2 v = __ldcg((const float2*)(xrow + d0));
            sX[d0 * 8 + bb] = v.x; sX[(d0 + 1) * 8 + bb] = v.y;
        }
        tgt += 16;
        gsync_wait_all(bg, tgt);          // barrier 1 wait: per-warp wakeup
        // (safe: our release fired only after owner warps' named bar, so
        //  owners' sAct reads are complete before any warp re-writes sAct)

        // ---- stage c ----
        {
            const float4* src = (const float4*)(g_c + bg * (H * BPG));
            *(float4*)&sAct[tid * 4] = __ldcg(&src[tid]);
        }
        __syncthreads();

        // ---- P2: z = tanh(c @ K1 + kb1) ----
        {
            uint64_t A0 = 0, A1 = 0, A2 = 0, A3 = 0;
            const int kb = p2chunk * 16;
#pragma unroll
            for (int kk = 0; kk < 16; kk++) {
                const float* cp = &sAct[(kb + kk) * 8];
                ulonglong2 pa = *(const ulonglong2*)cp;
                ulonglong2 pb = *(const ulonglong2*)(cp + 4);
                uint64_t W = pack2(wK1[kk]);
                ffma2(A0, pa.x, W); ffma2(A1, pa.y, W);
                ffma2(A2, pb.x, W); ffma2(A3, pb.y, W);
            }
            int base = p2chunk * 288 + p2m * 9;
            float2 f;
            f = unpk(A0); sRed[base + 0] = f.x; sRed[base + 1] = f.y;
            f = unpk(A1); sRed[base + 2] = f.x; sRed[base + 3] = f.y;
            f = unpk(A2); sRed[base + 4] = f.x; sRed[base + 5] = f.y;
            f = unpk(A3); sRed[base + 6] = f.x; sRed[base + 7] = f.y;
        }
        __syncthreads();
        if (tid < 256) {
            int mq = tid >> 3, bb = tid & 7;
            float d = 0.f;
#pragma unroll
            for (int c = 0; c < 16; c++) d += sRed[c * 288 + mq * 9 + bb];
            sZp[mq * 8 + (bb & 3) * 2 + (bb >> 2)] = ftanh(d + rkb1);
        }
        __syncthreads();

        // ---- P3 producer ----
        float2 f0, f1, f2, f3;
        {
            uint64_t A0 = 0, A1 = 0, A2 = 0, A3 = 0;
#pragma unroll
            for (int mm = 0; mm < 16; mm++) {
                const float* zp = &sZp[(p3mh * 16 + mm) * 8];
                ulonglong2 pa = *(const ulonglong2*)zp;
                ulonglong2 pb = *(const ulonglong2*)(zp + 4);
                uint64_t W = pack2(wK2[mm]);
                ffma2(A0, pa.x, W); ffma2(A1, pa.y, W);
                ffma2(A2, pb.x, W); ffma2(A3, pb.y, W);
            }
            f0 = unpk(A0); f1 = unpk(A1); f2 = unpk(A2); f3 = unpk(A3);
            if (p3mh == 1) {
                int base = p3n * 9;
                sRed[base + 0] = f0.x; sRed[base + 1] = f1.x; sRed[base + 2] = f2.x; sRed[base + 3] = f3.x;
                sRed[base + 4] = f0.y; sRed[base + 5] = f1.y; sRed[base + 6] = f2.y; sRed[base + 7] = f3.y;
            }
        }
        __syncthreads();
        if (tid < 256) {
            int base = p3n * 9;
            float4 lo = make_float4(f0.x + sRed[base + 0], f1.x + sRed[base + 1],
                                    f2.x + sRed[base + 2], f3.x + sRed[base + 3]);
            float4 hi = make_float4(f0.y + sRed[base + 4], f1.y + sRed[base + 5],
                                    f2.y + sRed[base + 6], f3.y + sRed[base + 7]);
            float* gp = &g_part[(((size_t)bg * 16 + cg) * H + p3n) * BPG];
            __stcg((float4*)gp, lo);
            __stcg((float4*)(gp + 4), hi);
            gsync_arrive_n(bg, 256);      // barrier 2 arrive: producers only
        }
        if (t + 1 < T) {                  // xproj(t+1) in wait slack
            uint64_t A0 = 0, A1 = 0, A2 = 0, A3 = 0;
            const int db = xdp * 16;
#pragma unroll
            for (int i = 0; i < 16; i++) {
                int d = db + i;
                ulonglong2 xa = *(const ulonglong2*)&sX[d * 8];
                ulonglong2 xb = *(const ulonglong2*)&sX[d * 8 + 4];
                uint64_t W = pack2(sW[d * 64 + xc]);
                ffma2(A0, xa.x, W); ffma2(A1, xa.y, W);
                ffma2(A2, xb.x, W); ffma2(A3, xb.y, W);
            }
            float* dst = &sXP[(xdp * 64 + xc) * 8];
            float2 g0 = unpk(A0), g1 = unpk(A1), g2 = unpk(A2), g3 = unpk(A3);
            dst[0] = g0.x; dst[1] = g0.y; dst[2] = g1.x; dst[3] = g1.y;
            dst[4] = g2.x; dst[5] = g2.y; dst[6] = g3.x; dst[7] = g3.y;
        }
        tgt += 16;
        gsync_wait_all(bg, tgt);          // barrier 2 wait: per-warp wakeup
        __syncthreads();                  // orders sXP writes before xpv reads

        // ---- P3 consumer: owner reads 16 partials directly ----
        if (tid < 128) {
            float ssum = 0.f;
#pragma unroll
            for (int j = 0; j < 16; j++)
                ssum += __ldcg(&g_part[(((size_t)bg * 16 + j) * H + n0 + onn) * BPG + obb]);
            float hn = oreg * ftanh(ssum + rkb2);
            __stcg(&g_h[bg * (H * BPG) + (n0 + onn) * BPG + obb], hn);
            gsync_arrive_n(bg, 128);      // barrier 3 arrive: producers only
        }
        if (t + 1 < T && tid < 128) {     // xpv regs in wait slack
#pragma unroll
            for (int g = 0; g < 4; g++) {
                int q = onn * 4 + g;
                float v = rb4[g];
#pragma unroll
                for (int dp = 0; dp < 8; dp++) v += sXP[(dp * 64 + q) * 8 + obb];
                xpv[g] = v;
            }
        }
        tgt += 16;
        gsync_wait_all(bg, tgt);          // barrier 3 wait: per-warp wakeup
        // (safe: next sAct writes precede a full stage-h __syncthreads, and
        //  prior-iteration sAct readers are covered by our own arrival)
    }

    // ---- epilogue: LN of h(T-1) ----
    {
        {
            const float4* src = (const float4*)(g_h + bg * (H * BPG));
            *(float4*)&sAct[tid * 4] = __ldcg(&src[tid]);
        }
        __syncthreads();
        {
            float s = 0.f, s2 = 0.f;
#pragma unroll
            for (int j = 0; j < 4; j++) {
                float v = sAct[tid + j * 512];
                s += v; s2 += v * v;
            }
            s  += __shfl_xor_sync(0xffffffffu, s, 8);
            s2 += __shfl_xor_sync(0xffffffffu, s2, 8);
            s  += __shfl_xor_sync(0xffffffffu, s, 16);
            s2 += __shfl_xor_sync(0xffffffffu, s2, 16);
            int lane = tid & 31, wp = tid >> 5;
            if (lane < 8) { sSt[wp * 16 + lane * 2] = s; sSt[wp * 16 + lane * 2 + 1] = s2; }
        }
        __syncthreads();
        if (tid < 128) {
            float ss = 0.f, qq = 0.f;
#pragma unroll
            for (int w = 0; w < 16; w++) {
                ss += sSt[w * 16 + obb * 2];
                qq += sSt[w * 16 + obb * 2 + 1];
            }
            float mu = ss * invH;
            float var = qq * invH - mu * mu;
            float rs = rsqrtf(var + EPS);
            float hr = sAct[(n0 + onn) * 8 + obb];
            float hn = (hr - mu) * rs * rgam + rbet;
            out[((size_t)(b0 + obb) * T + (T - 1)) * H + n0 + onn] = hn;
            if (has_hc) {
                out[(size_t)B * T * H + (size_t)(b0 + obb) * H + n0 + onn] = hn;
                out[(size_t)B * T * H + (size_t)B * H + (size_t)(b0 + obb) * H + n0 + onn] = creg;
            }
        }
    }
}

// ---------------- launch ----------------
extern "C" void kernel_launch(void* const* d_in, const int* in_sizes, int n_in,
                              void* d_out, int out_size)
{
    const float* x  = (const float*)d_in[0];
    const float* Wi = (const float*)d_in[1];  const float* bi = (const float*)d_in[2];
    const float* Wf = (const float*)d_in[3];  const float* bf = (const float*)d_in[4];
    const float* Wc = (const float*)d_in[5];  const float* bc = (const float*)d_in[6];
    const float* Wo = (const float*)d_in[7];  const float* bo = (const float*)d_in[8];
    const float* Ui = (const float*)d_in[9];  const float* Uf = (const float*)d_in[10];
    const float* Uc = (const float*)d_in[11]; const float* Uo = (const float*)d_in[12];
    const float* K1 = (const float*)d_in[13]; const float* kb1 = (const float*)d_in[14];
    const float* K2 = (const float*)d_in[15]; const float* kb2 = (const float*)d_in[16];
    const float* gamma = (const float*)d_in[17];
    const float* beta  = (const float*)d_in[18];
    float* out = (float*)d_out;

    const int has_hc = (out_size >= B * T * H + 2 * B * H) ? 1 : 0;

    // actual smem use ~83KB; pad to 120KB to force 1 CTA/SM spread
    const int smem_scan = 120 * 1024;

    cudaFuncSetAttribute(k_scan, cudaFuncAttributeMaxDynamicSharedMemorySize, smem_scan);

    k_init<<<1, 512>>>();
    k_dummy<<<1, 32>>>();
    k_dummy<<<1, 32>>>();
    k_scan<<<NCTA, NT, smem_scan>>>(x, Wi, bi, Wf, bf, Wc, bc, Wo, bo,
                                    Ui, Uf, Uc, Uo, K1, kb1, K2, kb2,
                                    gamma, beta, out, has_hc);
}